// round 14
// baseline (speedup 1.0000x reference)
#include <cuda_runtime.h>
#include <cuda_fp16.h>
#include <cstdint>
#include <cstddef>

// ===================== problem constants =====================
constexpr int B_SZ = 8;
constexpr int N_SZ = 2048;
constexpr int D_SZ = 128;

// ============ GEMM tiling: CTA 64(M) x 128(N) x 64(K), K_IT=32 ============
constexpr int K_IT = 32;
constexpr int A16_STG = 64 * 144;        // 9216 B (64 rows x 72 halves)
constexpr int B_STG = 128 * 144;         // 18432 B (128 rows x 72 halves)
constexpr int B_OFF = 2 * A16_STG;       // A16 ring-2 then B ring-3
constexpr unsigned DYN_B = B_OFF + 3 * B_STG + 256;  // 73984

// h kernel: one-shot fp16 MMA, 128x128 tile, K=128; smem rows 136 halves (272B)
constexpr int HSTRH = 136;                       // halves per row
constexpr unsigned DYN_H = 2u * 128 * HSTRH * 2 + 128;  // 69760

// scratch: hT[b][e][j] = fp16(leaky_relu(x @ W^T))^T
__device__ __half g_hT[(size_t)B_SZ * D_SZ * N_SZ];

// ===================== helpers =====================
__device__ __forceinline__ uint32_t s2u(const void* p) {
    uint32_t a;
    asm("{ .reg .u64 t; cvta.to.shared.u64 t, %1; cvt.u32.u64 %0, t; }" : "=r"(a) : "l"(p));
    return a;
}
__device__ __forceinline__ void cp16(uint32_t dst, const void* src) {
    asm volatile("cp.async.cg.shared.global [%0], [%1], 16;" :: "r"(dst), "l"(src));
}
__device__ __forceinline__ void mma_f16(float* d, const uint32_t* a,
                                        uint32_t b0, uint32_t b1) {
    asm volatile(
        "mma.sync.aligned.m16n8k16.row.col.f32.f16.f16.f32 "
        "{%0,%1,%2,%3}, {%4,%5,%6,%7}, {%8,%9}, {%0,%1,%2,%3};"
        : "+f"(d[0]), "+f"(d[1]), "+f"(d[2]), "+f"(d[3])
        : "r"(a[0]), "r"(a[1]), "r"(a[2]), "r"(a[3]), "r"(b0), "r"(b1));
}
#define LDSM4(r, addr)                                                          \
    asm volatile("ldmatrix.sync.aligned.m8n8.x4.shared.b16 {%0,%1,%2,%3}, [%4];" \
        : "=r"((r)[0]), "=r"((r)[1]), "=r"((r)[2]), "=r"((r)[3]) : "r"(addr))
__device__ __forceinline__ __half lrelu_h(float x) {
    float v = x > 0.f ? x : 0.01f * x;
    return __float2half_rn(v);
}
__device__ __forceinline__ uint32_t h2u(__half2 h) {
    return *reinterpret_cast<uint32_t*>(&h);
}

// ===================== kernel 1: hT = fp16(leaky_relu(x @ W^T))^T ===========
// one-shot: stage x-tile + W as fp16 in smem, 8 ks of fp16 MMA, transpose out
__global__ __launch_bounds__(256) void h_kernel(const float* __restrict__ x,
                                                const float* __restrict__ W) {
    extern __shared__ __half hs[];       // xs[128][136] then ws[128][136]
    const int tid = threadIdx.x;
    const int b = blockIdx.x >> 4;
    const int j0 = (blockIdx.x & 15) * 128;

    const int wid = tid >> 5;
    const int lane = tid & 31;
    const int g = lane >> 2;
    const int tg = lane & 3;
    const int wm = wid & 3;              // 4 row slices of 32 (j)
    const int wn = wid >> 2;             // 2 col slices of 64 (e)

    __half* xs = hs;
    __half* ws = hs + 128 * HSTRH;

    // ---- stage x tile and W as fp16 (row = tid>>1, half = tid&1) ----
    {
        const int row = tid >> 1;
        const int hh = tid & 1;
        const float* xsrc = x + ((size_t)b * N_SZ + j0 + row) * D_SZ + hh * 64;
        const float* wsrc = W + (size_t)row * D_SZ + hh * 64;
        __half* xdst = xs + row * HSTRH + hh * 64;
        __half* wdst = ws + row * HSTRH + hh * 64;
#pragma unroll
        for (int i = 0; i < 4; i++) {
            const float4* s = reinterpret_cast<const float4*>(xsrc + i * 16);
            float4 v0 = s[0], v1 = s[1], v2 = s[2], v3 = s[3];
            uint4 u0, u1;
            u0.x = h2u(__floats2half2_rn(v0.x, v0.y));
            u0.y = h2u(__floats2half2_rn(v0.z, v0.w));
            u0.z = h2u(__floats2half2_rn(v1.x, v1.y));
            u0.w = h2u(__floats2half2_rn(v1.z, v1.w));
            u1.x = h2u(__floats2half2_rn(v2.x, v2.y));
            u1.y = h2u(__floats2half2_rn(v2.z, v2.w));
            u1.z = h2u(__floats2half2_rn(v3.x, v3.y));
            u1.w = h2u(__floats2half2_rn(v3.z, v3.w));
            reinterpret_cast<uint4*>(xdst + i * 16)[0] = u0;
            reinterpret_cast<uint4*>(xdst + i * 16 + 8)[0] = u1;
        }
#pragma unroll
        for (int i = 0; i < 4; i++) {
            const float4* s = reinterpret_cast<const float4*>(wsrc + i * 16);
            float4 v0 = s[0], v1 = s[1], v2 = s[2], v3 = s[3];
            uint4 u0, u1;
            u0.x = h2u(__floats2half2_rn(v0.x, v0.y));
            u0.y = h2u(__floats2half2_rn(v0.z, v0.w));
            u0.z = h2u(__floats2half2_rn(v1.x, v1.y));
            u0.w = h2u(__floats2half2_rn(v1.z, v1.w));
            u1.x = h2u(__floats2half2_rn(v2.x, v2.y));
            u1.y = h2u(__floats2half2_rn(v2.z, v2.w));
            u1.z = h2u(__floats2half2_rn(v3.x, v3.y));
            u1.w = h2u(__floats2half2_rn(v3.z, v3.w));
            reinterpret_cast<uint4*>(wdst + i * 16)[0] = u0;
            reinterpret_cast<uint4*>(wdst + i * 16 + 8)[0] = u1;
        }
    }
    __syncthreads();

    // ---- MMA: warp tile 32(j) x 64(e), K=128 in 8 ks steps ----
    const uint32_t xbase = s2u(hs);
    const uint32_t aA0 = xbase + (uint32_t)((wm * 32 + (lane & 15)) * 272 +
                                            ((lane >> 4) * 16));
    const uint32_t aA1 = aA0 + 16 * 272;
    const uint32_t wbase = xbase + 128 * HSTRH * 2;
    const uint32_t bB = wbase + (uint32_t)((wn * 64 + (lane & 7) + ((lane >> 4) * 8)) * 272 +
                                           (((lane >> 3) & 1) * 16));

    float acc[2][8][4];
#pragma unroll
    for (int mt = 0; mt < 2; mt++)
#pragma unroll
        for (int nt = 0; nt < 8; nt++)
#pragma unroll
            for (int q = 0; q < 4; q++) acc[mt][nt][q] = 0.f;

#pragma unroll
    for (int ks = 0; ks < 8; ks++) {
        const uint32_t off = ks * 32;
        uint32_t a0[4], a1[4], f0[4], f1[4], f2[4], f3[4];
        LDSM4(a0, aA0 + off);
        LDSM4(a1, aA1 + off);
        LDSM4(f0, bB + off);
        LDSM4(f1, bB + 16 * 272 + off);
        LDSM4(f2, bB + 32 * 272 + off);
        LDSM4(f3, bB + 48 * 272 + off);
        mma_f16(acc[0][0], a0, f0[0], f0[1]);
        mma_f16(acc[0][1], a0, f0[2], f0[3]);
        mma_f16(acc[0][2], a0, f1[0], f1[1]);
        mma_f16(acc[0][3], a0, f1[2], f1[3]);
        mma_f16(acc[0][4], a0, f2[0], f2[1]);
        mma_f16(acc[0][5], a0, f2[2], f2[3]);
        mma_f16(acc[0][6], a0, f3[0], f3[1]);
        mma_f16(acc[0][7], a0, f3[2], f3[3]);
        mma_f16(acc[1][0], a1, f0[0], f0[1]);
        mma_f16(acc[1][1], a1, f0[2], f0[3]);
        mma_f16(acc[1][2], a1, f1[0], f1[1]);
        mma_f16(acc[1][3], a1, f1[2], f1[3]);
        mma_f16(acc[1][4], a1, f2[0], f2[1]);
        mma_f16(acc[1][5], a1, f2[2], f2[3]);
        mma_f16(acc[1][6], a1, f3[0], f3[1]);
        mma_f16(acc[1][7], a1, f3[2], f3[3]);
    }
    __syncthreads();                     // all smem reads done; reuse as transpose buf

    // ---- transpose through smem (hsm[e][j], stride 136 halves), store hT ----
    __half* hsm = hs;
#pragma unroll
    for (int mt = 0; mt < 2; mt++)
#pragma unroll
        for (int nt = 0; nt < 8; nt++) {
            int r = wm * 32 + mt * 16 + g;          // j
            int c = wn * 64 + nt * 8 + tg * 2;      // e
            hsm[c * HSTRH + r]           = lrelu_h(acc[mt][nt][0]);
            hsm[(c + 1) * HSTRH + r]     = lrelu_h(acc[mt][nt][1]);
            hsm[c * HSTRH + r + 8]       = lrelu_h(acc[mt][nt][2]);
            hsm[(c + 1) * HSTRH + r + 8] = lrelu_h(acc[mt][nt][3]);
        }
    __syncthreads();

    const int e = tid >> 1;
    const int jh = (tid & 1) * 64;
    uint4* dst = reinterpret_cast<uint4*>(g_hT + ((size_t)b * D_SZ + e) * N_SZ + j0 + jh);
    const uint4* src = reinterpret_cast<const uint4*>(hsm + e * HSTRH + jh);
#pragma unroll
    for (int q = 0; q < 8; q++) dst[q] = src[q];
}

// ===================== kernel 2: fused normalize + An @ h (fp16 MMA) ========
// out[b,i,e] = ( sum_j A[b,i,j] h[b,j,e] + (1 - A[b,i,i]) h[b,i,e] ) / d_i
// d_i = rowsum(A[b,i,:]) - A[b,i,i] + 1
// BK=64: A via LDG->regs (1-iter cover) -> STS fp16 ring-2; B cp.async ring-3
__global__ __launch_bounds__(256, 2) void gcn_gemm_kernel(const float* __restrict__ A,
                                                          const __half* __restrict__ hTg,
                                                          float* __restrict__ out) {
    extern __shared__ float dyn[];
    __shared__ float rs_sm[256];
    __shared__ float corr_sm[64];
    __shared__ float dinv_sm[64];

    const int tid = threadIdx.x;
    const int b = blockIdx.x >> 5;
    const int gi0 = (blockIdx.x & 31) * 64;

    const int wid = tid >> 5;
    const int lane = tid & 31;
    const int g = lane >> 2;
    const int tg = lane & 3;
    const int wm = wid & 1;      // 2 row slices of 32
    const int wn = wid >> 1;     // 4 col slices of 32

    const float* Ag = A + (size_t)b * N_SZ * N_SZ;
    const __half* hTb = hTg + (size_t)b * D_SZ * N_SZ;

    const uint32_t raw = s2u(dyn);
    const uint32_t base_u = (raw + 127u) & ~127u;
    char* dbase = reinterpret_cast<char*>(dyn) + (base_u - raw);

    // A path thread mapping: 4 threads/row, 16 consecutive floats each
    const int arow = tid >> 2;           // 0..63
    const int aq = tid & 3;              // quarter (16 floats)
    float rs = 0.f;

    // ldmatrix lane addresses (row stride 144 B = 72 halves, conflict-free)
    const uint32_t aAddr0 = base_u + (uint32_t)((wm * 32 + (lane & 15)) * 144 +
                                                ((lane >> 4) * 16));
    const uint32_t aAddr1 = aAddr0 + 16 * 144;
    const uint32_t bAddr0 = base_u + B_OFF +
        (uint32_t)((wn * 32 + (lane & 7) + ((lane >> 4) * 8)) * 144 +
                   (((lane >> 3) & 1) * 16));
    const uint32_t bAddr1 = bAddr0 + 16 * 144;

    float4 rv0, rv1, rv2, rv3;           // staged A tile (16 floats/thread)

    auto ldgA = [&](int t) {
        const float* p = Ag + (size_t)(gi0 + arow) * N_SZ + t * 64 + aq * 16;
        rv0 = *reinterpret_cast<const float4*>(p);
        rv1 = *reinterpret_cast<const float4*>(p + 4);
        rv2 = *reinterpret_cast<const float4*>(p + 8);
        rv3 = *reinterpret_cast<const float4*>(p + 12);
    };
    // STS fp16 (2x STS.128) + rowsum from the fp32 staged regs (counted once)
    auto stsA = [&](int slot) {
        uint4 u0, u1;
        u0.x = h2u(__floats2half2_rn(rv0.x, rv0.y));
        u0.y = h2u(__floats2half2_rn(rv0.z, rv0.w));
        u0.z = h2u(__floats2half2_rn(rv1.x, rv1.y));
        u0.w = h2u(__floats2half2_rn(rv1.z, rv1.w));
        u1.x = h2u(__floats2half2_rn(rv2.x, rv2.y));
        u1.y = h2u(__floats2half2_rn(rv2.z, rv2.w));
        u1.z = h2u(__floats2half2_rn(rv3.x, rv3.y));
        u1.w = h2u(__floats2half2_rn(rv3.z, rv3.w));
        uint4* p = reinterpret_cast<uint4*>(dbase + slot * A16_STG + arow * 144 + aq * 32);
        p[0] = u0;
        p[1] = u1;
        rs += ((rv0.x + rv0.y) + (rv0.z + rv0.w)) + ((rv1.x + rv1.y) + (rv1.z + rv1.w)) +
              ((rv2.x + rv2.y) + (rv2.z + rv2.w)) + ((rv3.x + rv3.y) + (rv3.z + rv3.w));
    };
    // B tile t -> given ring slot (128 e-rows x 64 halves, 4 cp16/thread)
    auto cpB = [&](int t, int slot) {
        const uint32_t bb = base_u + B_OFF + slot * B_STG;
#pragma unroll
        for (int i = 0; i < 4; i++) {
            int c2 = tid + i * 256;
            int e = c2 >> 3, ch = c2 & 7;
            cp16(bb + e * 144 + ch * 16,
                 hTb + (size_t)e * N_SZ + t * 64 + ch * 8);
        }
    };

    float acc[2][4][4];
#pragma unroll
    for (int mt = 0; mt < 2; mt++)
#pragma unroll
        for (int nt = 0; nt < 4; nt++)
#pragma unroll
            for (int q = 0; q < 4; q++) acc[mt][nt][q] = 0.f;

    // ---- prologue ----
    ldgA(0);
    cpB(0, 0);
    asm volatile("cp.async.commit_group;" ::: "memory");   // g0 = B0
    cpB(1, 1);
    asm volatile("cp.async.commit_group;" ::: "memory");   // g1 = B1
    stsA(0);                                               // tile0 -> A16 slot0 (one-time stall)
    ldgA(1);

    int sBr = 0, sBw = 2;
    for (int kt = 0; kt < K_IT; kt++) {
        asm volatile("cp.async.wait_group 1;" ::: "memory");  // B(kt) resident (per-thread)
        __syncthreads();                                       // all waits done; old slots dead

        if (kt + 2 < K_IT) cpB(kt + 2, sBw);                   // slot of B(kt-1): dead
        asm volatile("cp.async.commit_group;" ::: "memory");
        if (kt < K_IT - 1) stsA((kt + 1) & 1);                 // tile kt+1 from staged regs
        if (kt + 2 < K_IT) ldgA(kt + 2);                       // refill regs (1-iter cover)

        const uint32_t offA = (uint32_t)(kt & 1) * A16_STG;
        const uint32_t offB = (uint32_t)sBr * B_STG;

#pragma unroll
        for (int ks = 0; ks < 4; ks++) {
            uint32_t a0[4], a1[4], bf[4], cf[4];
            LDSM4(a0, aAddr0 + offA + ks * 32);
            LDSM4(a1, aAddr1 + offA + ks * 32);
            LDSM4(bf, bAddr0 + offB + ks * 32);
            LDSM4(cf, bAddr1 + offB + ks * 32);
            mma_f16(acc[0][0], a0, bf[0], bf[1]);
            mma_f16(acc[0][1], a0, bf[2], bf[3]);
            mma_f16(acc[0][2], a0, cf[0], cf[1]);
            mma_f16(acc[0][3], a0, cf[2], cf[3]);
            mma_f16(acc[1][0], a1, bf[0], bf[1]);
            mma_f16(acc[1][1], a1, bf[2], bf[3]);
            mma_f16(acc[1][2], a1, cf[0], cf[1]);
            mma_f16(acc[1][3], a1, cf[2], cf[3]);
        }
        sBr = (sBr == 2) ? 0 : sBr + 1;
        sBw = (sBw == 2) ? 0 : sBw + 1;
    }

    // ---- reductions & epilogue ----
    rs_sm[tid] = rs;
    __syncthreads();                    // all compute done, rings dead

    if (tid < 64) {
        const float* srcp = rs_sm + tid * 4;
        float d = (srcp[0] + srcp[1]) + (srcp[2] + srcp[3]);
        float aii = Ag[(size_t)(gi0 + tid) * (N_SZ + 1)];
        float c = 1.0f - aii;           // mask true: A>=0, rows strictly positive
        corr_sm[tid] = c;
        dinv_sm[tid] = 1.0f / (d + c);
    }

    float* o_sm = reinterpret_cast<float*>(dbase);            // [64][132] f32 (33792 B)
    float* hf = reinterpret_cast<float*>(dbase) + 64 * 132;   // [128][65] f32 (33280 B)
#pragma unroll
    for (int mt = 0; mt < 2; mt++)
#pragma unroll
        for (int nt = 0; nt < 4; nt++) {
            int r = wm * 32 + mt * 16 + g;
            int c = wn * 32 + nt * 8 + tg * 2;
            o_sm[r * 132 + c]           = acc[mt][nt][0];
            o_sm[r * 132 + c + 1]       = acc[mt][nt][1];
            o_sm[(r + 8) * 132 + c]     = acc[mt][nt][2];
            o_sm[(r + 8) * 132 + c + 1] = acc[mt][nt][3];
        }

    // load hT[:, gi0..gi0+64) tile -> float smem (for diag correction)
    {
        const int e = tid >> 1;
        const int part = tid & 1;
        const uint4* src = reinterpret_cast<const uint4*>(
            hTb + (size_t)e * N_SZ + gi0 + part * 32);
#pragma unroll
        for (int q = 0; q < 4; q++) {
            uint4 v = src[q];
            uint32_t w[4] = {v.x, v.y, v.z, v.w};
#pragma unroll
            for (int u = 0; u < 4; u++) {
                float2 f = __half22float2(*reinterpret_cast<__half2*>(&w[u]));
                hf[e * 65 + part * 32 + q * 8 + u * 2]     = f.x;
                hf[e * 65 + part * 32 + q * 8 + u * 2 + 1] = f.y;
            }
        }
    }
    __syncthreads();

    float* ob = out + ((size_t)b * N_SZ + gi0) * D_SZ;
#pragma unroll 8
    for (int i = tid; i < 64 * 128; i += 256) {
        int r = i >> 7, e = i & 127;
        ob[i] = (o_sm[r * 132 + e] + corr_sm[r] * hf[e * 65 + r]) * dinv_sm[r];
    }
}

// ===================== host =====================
extern "C" void kernel_launch(void* const* d_in, const int* in_sizes, int n_in,
                              void* d_out, int out_size) {
    const float* x = (const float*)d_in[0];
    const float* A = (const float*)d_in[1];
    const float* W = (const float*)d_in[2];
    float* out = (float*)d_out;

    void* hT_ptr = nullptr;
    cudaGetSymbolAddress(&hT_ptr, g_hT);

    cudaFuncSetAttribute(h_kernel, cudaFuncAttributeMaxDynamicSharedMemorySize, DYN_H);
    h_kernel<<<B_SZ * (N_SZ / 128), 256, DYN_H>>>(x, W);

    cudaFuncSetAttribute(gcn_gemm_kernel, cudaFuncAttributeMaxDynamicSharedMemorySize, DYN_B);
    gcn_gemm_kernel<<<B_SZ * (N_SZ / 64), 256, DYN_B>>>(A, (const __half*)hT_ptr, out);
    (void)in_sizes; (void)n_in; (void)out_size;
}

// round 15
// speedup vs baseline: 1.0491x; 1.0491x over previous
#include <cuda_runtime.h>
#include <cuda_fp16.h>
#include <cstdint>
#include <cstddef>

// ===================== problem constants =====================
constexpr int B_SZ = 8;
constexpr int N_SZ = 2048;
constexpr int D_SZ = 128;

// ============ GEMM tiling: CTA 64(M) x 128(N) x 64(K), K_IT=32 ============
constexpr int K_IT = 32;
constexpr int A16_STG = 64 * 144;        // 9216 B (64 rows x 72 halves)
constexpr int B_STG = 128 * 144;         // 18432 B (128 rows x 72 halves)
constexpr int B_OFF = 2 * A16_STG;       // A16 ring-2 then B ring-3
constexpr unsigned DYN_B = B_OFF + 3 * B_STG + 256;  // 73984

// h kernel: cp.async fp32 staging + one-shot fp16 MMA
constexpr int HSTRH = 136;                           // fp16 row stride (halves)
constexpr int STG32_B = 2 * 128 * 128 * 4;           // 131072 B fp32 staging (x+W)
constexpr unsigned DYN_H = STG32_B + 2u * 128 * HSTRH * 2 + 128;  // ~200832

// scratch: hT[b][e][j] = fp16(leaky_relu(x @ W^T))^T
__device__ __half g_hT[(size_t)B_SZ * D_SZ * N_SZ];

// ===================== helpers =====================
__device__ __forceinline__ uint32_t s2u(const void* p) {
    uint32_t a;
    asm("{ .reg .u64 t; cvta.to.shared.u64 t, %1; cvt.u32.u64 %0, t; }" : "=r"(a) : "l"(p));
    return a;
}
__device__ __forceinline__ void cp16(uint32_t dst, const void* src) {
    asm volatile("cp.async.cg.shared.global [%0], [%1], 16;" :: "r"(dst), "l"(src));
}
__device__ __forceinline__ void mma_f16(float* d, const uint32_t* a,
                                        uint32_t b0, uint32_t b1) {
    asm volatile(
        "mma.sync.aligned.m16n8k16.row.col.f32.f16.f16.f32 "
        "{%0,%1,%2,%3}, {%4,%5,%6,%7}, {%8,%9}, {%0,%1,%2,%3};"
        : "+f"(d[0]), "+f"(d[1]), "+f"(d[2]), "+f"(d[3])
        : "r"(a[0]), "r"(a[1]), "r"(a[2]), "r"(a[3]), "r"(b0), "r"(b1));
}
#define LDSM4(r, addr)                                                          \
    asm volatile("ldmatrix.sync.aligned.m8n8.x4.shared.b16 {%0,%1,%2,%3}, [%4];" \
        : "=r"((r)[0]), "=r"((r)[1]), "=r"((r)[2]), "=r"((r)[3]) : "r"(addr))
__device__ __forceinline__ __half lrelu_h(float x) {
    float v = x > 0.f ? x : 0.01f * x;
    return __float2half_rn(v);
}
__device__ __forceinline__ uint32_t h2u(__half2 h) {
    return *reinterpret_cast<uint32_t*>(&h);
}

// ===================== kernel 1: hT = fp16(leaky_relu(x @ W^T))^T ===========
// cp.async fp32 staging -> smem convert -> one-shot fp16 MMA -> transpose out
__global__ __launch_bounds__(256) void h_kernel(const float* __restrict__ x,
                                                const float* __restrict__ W) {
    extern __shared__ char hraw[];
    const int tid = threadIdx.x;
    const int b = blockIdx.x >> 4;
    const int j0 = (blockIdx.x & 15) * 128;

    const int wid = tid >> 5;
    const int lane = tid & 31;
    const int g = lane >> 2;
    const int tg = lane & 3;
    const int wm = wid & 3;              // 4 row slices of 32 (j)
    const int wn = wid >> 2;             // 2 col slices of 64 (e)

    float* stgx = reinterpret_cast<float*>(hraw);            // [128][128] fp32
    float* stgw = stgx + 128 * 128;                          // [128][128] fp32
    __half* xs = reinterpret_cast<__half*>(hraw + STG32_B);  // [128][136] fp16
    __half* ws = xs + 128 * HSTRH;                           // [128][136] fp16

    const uint32_t stgx_u = s2u(stgx);
    const uint32_t stgw_u = s2u(stgw);
    const float* xg = x + ((size_t)b * N_SZ + j0) * D_SZ;

    // ---- stage fp32 via cp.async (fire-and-forget; 32 cp16/thread) ----
#pragma unroll
    for (int i = 0; i < 16; i++) {
        int c = tid + i * 256;           // float4 index, 0..4095
        int r = c >> 5, q = c & 31;
        cp16(stgx_u + c * 16, xg + (size_t)r * D_SZ + q * 4);
        cp16(stgw_u + c * 16, W + (size_t)r * D_SZ + q * 4);
    }
    asm volatile("cp.async.commit_group;" ::: "memory");
    asm volatile("cp.async.wait_group 0;" ::: "memory");
    __syncthreads();

    // ---- convert pass: smem fp32 -> smem fp16 (pipelined LDS, no DRAM stall) ----
    {
        const float4* sx = reinterpret_cast<const float4*>(stgx);
        const float4* sw = reinterpret_cast<const float4*>(stgw);
#pragma unroll
        for (int i = 0; i < 16; i++) {
            int c = tid + i * 256;
            int r = c >> 5, q = c & 31;
            float4 vx = sx[c];
            float4 vw = sw[c];
            uint2 ux, uw;
            ux.x = h2u(__floats2half2_rn(vx.x, vx.y));
            ux.y = h2u(__floats2half2_rn(vx.z, vx.w));
            uw.x = h2u(__floats2half2_rn(vw.x, vw.y));
            uw.y = h2u(__floats2half2_rn(vw.z, vw.w));
            *reinterpret_cast<uint2*>(xs + r * HSTRH + q * 4) = ux;
            *reinterpret_cast<uint2*>(ws + r * HSTRH + q * 4) = uw;
        }
    }
    __syncthreads();

    // ---- MMA: warp tile 32(j) x 64(e), K=128 in 8 ks steps ----
    const uint32_t xb = s2u(xs);
    const uint32_t wb = s2u(ws);
    const uint32_t aA0 = xb + (uint32_t)((wm * 32 + (lane & 15)) * 272 +
                                         ((lane >> 4) * 16));
    const uint32_t aA1 = aA0 + 16 * 272;
    const uint32_t bB = wb + (uint32_t)((wn * 64 + (lane & 7) + ((lane >> 4) * 8)) * 272 +
                                        (((lane >> 3) & 1) * 16));

    float acc[2][8][4];
#pragma unroll
    for (int mt = 0; mt < 2; mt++)
#pragma unroll
        for (int nt = 0; nt < 8; nt++)
#pragma unroll
            for (int q = 0; q < 4; q++) acc[mt][nt][q] = 0.f;

#pragma unroll
    for (int ks = 0; ks < 8; ks++) {
        const uint32_t off = ks * 32;
        uint32_t a0[4], a1[4], f0[4], f1[4], f2[4], f3[4];
        LDSM4(a0, aA0 + off);
        LDSM4(a1, aA1 + off);
        LDSM4(f0, bB + off);
        LDSM4(f1, bB + 16 * 272 + off);
        LDSM4(f2, bB + 32 * 272 + off);
        LDSM4(f3, bB + 48 * 272 + off);
        mma_f16(acc[0][0], a0, f0[0], f0[1]);
        mma_f16(acc[0][1], a0, f0[2], f0[3]);
        mma_f16(acc[0][2], a0, f1[0], f1[1]);
        mma_f16(acc[0][3], a0, f1[2], f1[3]);
        mma_f16(acc[0][4], a0, f2[0], f2[1]);
        mma_f16(acc[0][5], a0, f2[2], f2[3]);
        mma_f16(acc[0][6], a0, f3[0], f3[1]);
        mma_f16(acc[0][7], a0, f3[2], f3[3]);
        mma_f16(acc[1][0], a1, f0[0], f0[1]);
        mma_f16(acc[1][1], a1, f0[2], f0[3]);
        mma_f16(acc[1][2], a1, f1[0], f1[1]);
        mma_f16(acc[1][3], a1, f1[2], f1[3]);
        mma_f16(acc[1][4], a1, f2[0], f2[1]);
        mma_f16(acc[1][5], a1, f2[2], f2[3]);
        mma_f16(acc[1][6], a1, f3[0], f3[1]);
        mma_f16(acc[1][7], a1, f3[2], f3[3]);
    }
    __syncthreads();                     // all smem reads done; reuse xs as transpose buf

    // ---- transpose through smem (hsm[e][j], stride 136 halves), store hT ----
    __half* hsm = xs;
#pragma unroll
    for (int mt = 0; mt < 2; mt++)
#pragma unroll
        for (int nt = 0; nt < 8; nt++) {
            int r = wm * 32 + mt * 16 + g;          // j
            int c = wn * 64 + nt * 8 + tg * 2;      // e
            hsm[c * HSTRH + r]           = lrelu_h(acc[mt][nt][0]);
            hsm[(c + 1) * HSTRH + r]     = lrelu_h(acc[mt][nt][1]);
            hsm[c * HSTRH + r + 8]       = lrelu_h(acc[mt][nt][2]);
            hsm[(c + 1) * HSTRH + r + 8] = lrelu_h(acc[mt][nt][3]);
        }
    __syncthreads();

    const int e = tid >> 1;
    const int jh = (tid & 1) * 64;
    uint4* dst = reinterpret_cast<uint4*>(g_hT + ((size_t)b * D_SZ + e) * N_SZ + j0 + jh);
    const uint4* src = reinterpret_cast<const uint4*>(hsm + e * HSTRH + jh);
#pragma unroll
    for (int q = 0; q < 8; q++) dst[q] = src[q];
}

// ===================== kernel 2: fused normalize + An @ h (fp16 MMA) ========
// out[b,i,e] = ( sum_j A[b,i,j] h[b,j,e] + (1 - A[b,i,i]) h[b,i,e] ) / d_i
// d_i = rowsum(A[b,i,:]) - A[b,i,i] + 1
// BK=64: A via LDG->regs (1-iter cover) -> STS fp16 ring-2; B cp.async ring-3
__global__ __launch_bounds__(256, 2) void gcn_gemm_kernel(const float* __restrict__ A,
                                                          const __half* __restrict__ hTg,
                                                          float* __restrict__ out) {
    extern __shared__ float dyn[];
    __shared__ float rs_sm[256];
    __shared__ float corr_sm[64];
    __shared__ float dinv_sm[64];

    const int tid = threadIdx.x;
    const int b = blockIdx.x >> 5;
    const int gi0 = (blockIdx.x & 31) * 64;

    const int wid = tid >> 5;
    const int lane = tid & 31;
    const int g = lane >> 2;
    const int tg = lane & 3;
    const int wm = wid & 1;      // 2 row slices of 32
    const int wn = wid >> 1;     // 4 col slices of 32

    const float* Ag = A + (size_t)b * N_SZ * N_SZ;
    const __half* hTb = hTg + (size_t)b * D_SZ * N_SZ;

    const uint32_t raw = s2u(dyn);
    const uint32_t base_u = (raw + 127u) & ~127u;
    char* dbase = reinterpret_cast<char*>(dyn) + (base_u - raw);

    // A path thread mapping: 4 threads/row, 16 consecutive floats each
    const int arow = tid >> 2;           // 0..63
    const int aq = tid & 3;              // quarter (16 floats)
    float rs = 0.f;

    // ldmatrix lane addresses (row stride 144 B = 72 halves, conflict-free)
    const uint32_t aAddr0 = base_u + (uint32_t)((wm * 32 + (lane & 15)) * 144 +
                                                ((lane >> 4) * 16));
    const uint32_t aAddr1 = aAddr0 + 16 * 144;
    const uint32_t bAddr0 = base_u + B_OFF +
        (uint32_t)((wn * 32 + (lane & 7) + ((lane >> 4) * 8)) * 144 +
                   (((lane >> 3) & 1) * 16));
    const uint32_t bAddr1 = bAddr0 + 16 * 144;

    float4 rv0, rv1, rv2, rv3;           // staged A tile (16 floats/thread)

    auto ldgA = [&](int t) {
        const float* p = Ag + (size_t)(gi0 + arow) * N_SZ + t * 64 + aq * 16;
        rv0 = *reinterpret_cast<const float4*>(p);
        rv1 = *reinterpret_cast<const float4*>(p + 4);
        rv2 = *reinterpret_cast<const float4*>(p + 8);
        rv3 = *reinterpret_cast<const float4*>(p + 12);
    };
    // STS fp16 (2x STS.128) + rowsum from the fp32 staged regs (counted once)
    auto stsA = [&](int slot) {
        uint4 u0, u1;
        u0.x = h2u(__floats2half2_rn(rv0.x, rv0.y));
        u0.y = h2u(__floats2half2_rn(rv0.z, rv0.w));
        u0.z = h2u(__floats2half2_rn(rv1.x, rv1.y));
        u0.w = h2u(__floats2half2_rn(rv1.z, rv1.w));
        u1.x = h2u(__floats2half2_rn(rv2.x, rv2.y));
        u1.y = h2u(__floats2half2_rn(rv2.z, rv2.w));
        u1.z = h2u(__floats2half2_rn(rv3.x, rv3.y));
        u1.w = h2u(__floats2half2_rn(rv3.z, rv3.w));
        uint4* p = reinterpret_cast<uint4*>(dbase + slot * A16_STG + arow * 144 + aq * 32);
        p[0] = u0;
        p[1] = u1;
        rs += ((rv0.x + rv0.y) + (rv0.z + rv0.w)) + ((rv1.x + rv1.y) + (rv1.z + rv1.w)) +
              ((rv2.x + rv2.y) + (rv2.z + rv2.w)) + ((rv3.x + rv3.y) + (rv3.z + rv3.w));
    };
    // B tile t -> given ring slot (128 e-rows x 64 halves, 4 cp16/thread)
    auto cpB = [&](int t, int slot) {
        const uint32_t bb = base_u + B_OFF + slot * B_STG;
#pragma unroll
        for (int i = 0; i < 4; i++) {
            int c2 = tid + i * 256;
            int e = c2 >> 3, ch = c2 & 7;
            cp16(bb + e * 144 + ch * 16,
                 hTb + (size_t)e * N_SZ + t * 64 + ch * 8);
        }
    };

    float acc[2][4][4];
#pragma unroll
    for (int mt = 0; mt < 2; mt++)
#pragma unroll
        for (int nt = 0; nt < 4; nt++)
#pragma unroll
            for (int q = 0; q < 4; q++) acc[mt][nt][q] = 0.f;

    // ---- prologue ----
    ldgA(0);
    cpB(0, 0);
    asm volatile("cp.async.commit_group;" ::: "memory");   // g0 = B0
    cpB(1, 1);
    asm volatile("cp.async.commit_group;" ::: "memory");   // g1 = B1
    stsA(0);                                               // tile0 -> A16 slot0 (one-time stall)
    ldgA(1);

    int sBr = 0, sBw = 2;
    for (int kt = 0; kt < K_IT; kt++) {
        asm volatile("cp.async.wait_group 1;" ::: "memory");  // B(kt) resident (per-thread)
        __syncthreads();                                       // all waits done; old slots dead

        if (kt + 2 < K_IT) cpB(kt + 2, sBw);                   // slot of B(kt-1): dead
        asm volatile("cp.async.commit_group;" ::: "memory");
        if (kt < K_IT - 1) stsA((kt + 1) & 1);                 // tile kt+1 from staged regs
        if (kt + 2 < K_IT) ldgA(kt + 2);                       // refill regs (1-iter cover)

        const uint32_t offA = (uint32_t)(kt & 1) * A16_STG;
        const uint32_t offB = (uint32_t)sBr * B_STG;

#pragma unroll
        for (int ks = 0; ks < 4; ks++) {
            uint32_t a0[4], a1[4], bf[4], cf[4];
            LDSM4(a0, aAddr0 + offA + ks * 32);
            LDSM4(a1, aAddr1 + offA + ks * 32);
            LDSM4(bf, bAddr0 + offB + ks * 32);
            LDSM4(cf, bAddr1 + offB + ks * 32);
            mma_f16(acc[0][0], a0, bf[0], bf[1]);
            mma_f16(acc[0][1], a0, bf[2], bf[3]);
            mma_f16(acc[0][2], a0, cf[0], cf[1]);
            mma_f16(acc[0][3], a0, cf[2], cf[3]);
            mma_f16(acc[1][0], a1, bf[0], bf[1]);
            mma_f16(acc[1][1], a1, bf[2], bf[3]);
            mma_f16(acc[1][2], a1, cf[0], cf[1]);
            mma_f16(acc[1][3], a1, cf[2], cf[3]);
        }
        sBr = (sBr == 2) ? 0 : sBr + 1;
        sBw = (sBw == 2) ? 0 : sBw + 1;
    }

    // ---- reductions & epilogue ----
    rs_sm[tid] = rs;
    __syncthreads();                    // all compute done, rings dead

    if (tid < 64) {
        const float* srcp = rs_sm + tid * 4;
        float d = (srcp[0] + srcp[1]) + (srcp[2] + srcp[3]);
        float aii = Ag[(size_t)(gi0 + tid) * (N_SZ + 1)];
        float c = 1.0f - aii;           // mask true: A>=0, rows strictly positive
        corr_sm[tid] = c;
        dinv_sm[tid] = 1.0f / (d + c);
    }

    float* o_sm = reinterpret_cast<float*>(dbase);            // [64][132] f32 (33792 B)
    float* hf = reinterpret_cast<float*>(dbase) + 64 * 132;   // [128][65] f32 (33280 B)
#pragma unroll
    for (int mt = 0; mt < 2; mt++)
#pragma unroll
        for (int nt = 0; nt < 4; nt++) {
            int r = wm * 32 + mt * 16 + g;
            int c = wn * 32 + nt * 8 + tg * 2;
            o_sm[r * 132 + c]           = acc[mt][nt][0];
            o_sm[r * 132 + c + 1]       = acc[mt][nt][1];
            o_sm[(r + 8) * 132 + c]     = acc[mt][nt][2];
            o_sm[(r + 8) * 132 + c + 1] = acc[mt][nt][3];
        }

    // load hT[:, gi0..gi0+64) tile -> float smem (for diag correction)
    {
        const int e = tid >> 1;
        const int part = tid & 1;
        const uint4* src = reinterpret_cast<const uint4*>(
            hTb + (size_t)e * N_SZ + gi0 + part * 32);
#pragma unroll
        for (int q = 0; q < 4; q++) {
            uint4 v = src[q];
            uint32_t w[4] = {v.x, v.y, v.z, v.w};
#pragma unroll
            for (int u = 0; u < 4; u++) {
                float2 f = __half22float2(*reinterpret_cast<__half2*>(&w[u]));
                hf[e * 65 + part * 32 + q * 8 + u * 2]     = f.x;
                hf[e * 65 + part * 32 + q * 8 + u * 2 + 1] = f.y;
            }
        }
    }
    __syncthreads();

    float* ob = out + ((size_t)b * N_SZ + gi0) * D_SZ;
#pragma unroll 8
    for (int i = tid; i < 64 * 128; i += 256) {
        int r = i >> 7, e = i & 127;
        ob[i] = (o_sm[r * 132 + e] + corr_sm[r] * hf[e * 65 + r]) * dinv_sm[r];
    }
}

// ===================== host =====================
extern "C" void kernel_launch(void* const* d_in, const int* in_sizes, int n_in,
                              void* d_out, int out_size) {
    const float* x = (const float*)d_in[0];
    const float* A = (const float*)d_in[1];
    const float* W = (const float*)d_in[2];
    float* out = (float*)d_out;

    void* hT_ptr = nullptr;
    cudaGetSymbolAddress(&hT_ptr, g_hT);

    cudaFuncSetAttribute(h_kernel, cudaFuncAttributeMaxDynamicSharedMemorySize, DYN_H);
    h_kernel<<<B_SZ * (N_SZ / 128), 256, DYN_H>>>(x, W);

    cudaFuncSetAttribute(gcn_gemm_kernel, cudaFuncAttributeMaxDynamicSharedMemorySize, DYN_B);
    gcn_gemm_kernel<<<B_SZ * (N_SZ / 64), 256, DYN_B>>>(A, (const __half*)hT_ptr, out);
    (void)in_sizes; (void)n_in; (void)out_size;
}